// round 9
// baseline (speedup 1.0000x reference)
#include <cuda_runtime.h>
#include <cuda_fp16.h>
#include <cstdint>

#define BETA   0.95f
#define THRESH 1.0f

constexpr int NI = 80, NH = 256, NC = 2, T = 200, BATCH = 4096;
constexpr int NB = 32, NBLK = BATCH / NB, NTHR = 512;   // 16 warps, j-tile 16

// Per-warp A-frag stream (dedup'd): L1: 10 (kc0..4 x {hi,lo}), L2: 32, L3: 32
constexpr int FPW = 74, L2BASE = 10, L3BASE = 42;
__device__ __align__(16) __half g_wfrag[16 * FPW * 256];   // 606 KB, L2-resident

// Conflict-free strides (LDS.32 pattern: word%32 = r*4+q, bijective)
constexpr int SKX = 88;    // x tiles [32 b][80 i] halfs
constexpr int SKS = 264;   // spike tiles [32 b][256 i] halfs

// ---- prep: pack split weights into m16n8k16 A-frag lane order ----
__global__ void prep(const float* __restrict__ W1, const float* __restrict__ W2,
                     const float* __restrict__ W3) {
    int idx = blockIdx.x * 256 + threadIdx.x;      // 16*74*256
    if (idx >= 16 * FPW * 256) return;
    int h = idx & 7;
    int l = (idx >> 3) & 31;
    int f = (idx >> 8) % FPW;
    int w = (idx >> 8) / FPW;
    const float* W; int K, kc, split;
    if (f < L2BASE)      { kc = f >> 1; split = f & 1; W = W1; K = NI; }
    else if (f < L3BASE) { int g = f - L2BASE; kc = g >> 1; split = g & 1; W = W2; K = NH; }
    else                 { int g = f - L3BASE; kc = g >> 1; split = g & 1; W = W3; K = NH; }
    int r = (l >> 2) + ((h >> 1) & 1) * 8;
    int k = (l & 3) * 2 + (h & 1) + ((h >> 2) & 1) * 8;
    int j = w * 16 + r;
    int i = kc * 16 + k;
    float v = W[j * K + i];
    __half hv = __float2half_rn(v);
    if (split) hv = __float2half_rn(v - __half2float(hv));
    g_wfrag[idx] = hv;
}

__device__ __forceinline__ void mma16816(float* d, uint4 a, uint32_t b0, uint32_t b1) {
    asm volatile(
        "mma.sync.aligned.m16n8k16.row.col.f32.f16.f16.f32 "
        "{%0,%1,%2,%3}, {%4,%5,%6,%7}, {%8,%9}, {%0,%1,%2,%3};"
        : "+f"(d[0]), "+f"(d[1]), "+f"(d[2]), "+f"(d[3])
        : "r"(a.x), "r"(a.y), "r"(a.z), "r"(a.w), "r"(b0), "r"(b1));
}

// L2/L3: D[16j x 32b] += Wsplit * spikes. Depth-2 A-frag pipeline.
__device__ __forceinline__ void gemm256(const __half* __restrict__ sB,
                                        const uint4* __restrict__ ab, int base,
                                        float acc[4][4], int l, uint4 p0, uint4 p1) {
    const int q2 = (l & 3) * 2, rw = (l >> 2);
    uint4 pipe[4];
    pipe[0] = p0;                                   // kc0 (cross-barrier prefetch)
    pipe[1] = p1;
    pipe[2] = ab[(base + 2) * 32 + l];              // kc1
    pipe[3] = ab[(base + 3) * 32 + l];
#pragma unroll
    for (int kc = 0; kc < 16; kc++) {
        const int cur = (kc & 1) * 2;
        uint4 a0 = pipe[cur], a1 = pipe[cur + 1];
        if (kc < 14) {
            pipe[cur]     = ab[(base + 2 * kc + 4) * 32 + l];
            pipe[cur + 1] = ab[(base + 2 * kc + 5) * 32 + l];
        }
        uint32_t bf[4][2];
#pragma unroll
        for (int nt = 0; nt < 4; nt++) {
            const uint32_t* p = (const uint32_t*)(sB + (nt * 8 + rw) * SKS + kc * 16 + q2);
            bf[nt][0] = p[0];
            bf[nt][1] = p[4];          // k+8
        }
#pragma unroll
        for (int nt = 0; nt < 4; nt++) mma16816(acc[nt], a0, bf[nt][0], bf[nt][1]);
#pragma unroll
        for (int nt = 0; nt < 4; nt++) mma16816(acc[nt], a1, bf[nt][0], bf[nt][1]);
    }
}

// L1: products hiW*hiX, hiW*loX, loW*hiX over K=80. Depth-2 pipeline.
__device__ __forceinline__ void gemm80(const __half* __restrict__ sXhi,
                                       const __half* __restrict__ sXlo,
                                       const uint4* __restrict__ ab,
                                       float acc[4][4], int l, uint4 p0, uint4 p1) {
    const int q2 = (l & 3) * 2, rw = (l >> 2);
    uint4 pipe[4];
    pipe[0] = p0;                                   // kc0 hi
    pipe[1] = p1;                                   // kc0 lo
    pipe[2] = ab[2 * 32 + l];                       // kc1 hi
    pipe[3] = ab[3 * 32 + l];                       // kc1 lo
#pragma unroll
    for (int kc = 0; kc < 5; kc++) {
        const int cur = (kc & 1) * 2;
        uint4 ah = pipe[cur], al = pipe[cur + 1];
        if (kc < 3) {
            pipe[cur]     = ab[(2 * kc + 4) * 32 + l];
            pipe[cur + 1] = ab[(2 * kc + 5) * 32 + l];
        }
        uint32_t bh[4][2], bl[4][2];
#pragma unroll
        for (int nt = 0; nt < 4; nt++) {
            int off = (nt * 8 + rw) * SKX + kc * 16 + q2;
            const uint32_t* ph = (const uint32_t*)(sXhi + off);
            const uint32_t* pl = (const uint32_t*)(sXlo + off);
            bh[nt][0] = ph[0]; bh[nt][1] = ph[4];
            bl[nt][0] = pl[0]; bl[nt][1] = pl[4];
        }
#pragma unroll
        for (int nt = 0; nt < 4; nt++) mma16816(acc[nt], ah, bh[nt][0], bh[nt][1]);
#pragma unroll
        for (int nt = 0; nt < 4; nt++) mma16816(acc[nt], ah, bl[nt][0], bl[nt][1]);
#pragma unroll
        for (int nt = 0; nt < 4; nt++) mma16816(acc[nt], al, bh[nt][0], bh[nt][1]);
    }
}

__global__ void __launch_bounds__(NTHR) snn_kernel(
    const float* __restrict__ x,
    const float* __restrict__ B1, const float* __restrict__ B2,
    const float* __restrict__ B3, const float* __restrict__ W4,
    const float* __restrict__ b4, float* __restrict__ out)
{
    extern __shared__ __align__(16) char smem[];
    __half* sXhi = (__half*)smem;                  // 32*88
    __half* sXlo = sXhi + 32 * SKX;
    __half* sS1  = sXlo + 32 * SKX;                // 32*264
    __half* sS2  = sS1 + 32 * SKS;
    float*  s3f  = (float*)(sS2 + 32 * SKS);       // [256 j][33]
    float*  w4s  = s3f + 256 * 33;                 // 512
    float*  m3f  = w4s + NC * NH;                  // [256 j][33] membrane L3

    const int tid = threadIdx.x, l = tid & 31, w = tid >> 5;
    const int b0 = blockIdx.x * NB;
    const int jw = w * 16;
    const uint4* ab = ((const uint4*)g_wfrag) + (size_t)w * FPW * 32;

    float bias1[2], bias2[2], bias3[2];
#pragma unroll
    for (int rh = 0; rh < 2; rh++) {
        int j = jw + (l >> 2) + rh * 8;
        bias1[rh] = B1[j]; bias2[rh] = B2[j]; bias3[rh] = B3[j];
    }

    float m1[4][4], m2[4][4];
#pragma unroll
    for (int nt = 0; nt < 4; nt++)
#pragma unroll
        for (int d = 0; d < 4; d++) { m1[nt][d] = 0.f; m2[nt][d] = 0.f; }

    // layer-4 ownership: 8 threads per output o; part-0 thread owns m4
    const int o4 = tid >> 3, part = tid & 7;
    const int bb4 = o4 >> 1, cc4 = o4 & 1;
    float m4v = 0.f, b4v = (part == 0) ? b4[cc4] : 0.f;

    for (int k = tid; k < NC * NH; k += NTHR) w4s[k] = W4[k];
    for (int k = tid; k < 256 * 33; k += NTHR) m3f[k] = 0.f;

    // stage x for t=0
    for (int k = tid; k < NI * NB; k += NTHR) {
        int i = k >> 5, b = k & 31;
        float v = x[((size_t)(b0 + b) * NI + i) * T];
        __half hh = __float2half_rn(v);
        __half hl = __float2half_rn(v - __half2float(hh));
        sXhi[b * SKX + i] = hh;
        sXlo[b * SKX + i] = hl;
    }
    uint4 p0 = ab[0 * 32 + l], p1 = ab[1 * 32 + l];   // L1 kc=0 prefetch
    __syncthreads();

    for (int t = 0; t < T; t++) {
        float acc[4][4];

        // ---- layer 1 ----
#pragma unroll
        for (int nt = 0; nt < 4; nt++)
#pragma unroll
            for (int d = 0; d < 4; d++) acc[nt][d] = 0.f;
        gemm80(sXhi, sXlo, ab, acc, l, p0, p1);
#pragma unroll
        for (int nt = 0; nt < 4; nt++)
#pragma unroll
            for (int d = 0; d < 4; d++) {
                int rh = d >> 1, c = d & 1;
                float cur = acc[nt][d] + bias1[rh];
                float mo = m1[nt][d];
                float mn = BETA * mo + cur - ((mo > THRESH) ? THRESH : 0.0f);
                m1[nt][d] = mn;
                int j = jw + (l >> 2) + rh * 8;
                int b = nt * 8 + (l & 3) * 2 + c;
                sS1[b * SKS + j] = (mn > THRESH) ? __ushort_as_half((unsigned short)0x3C00)
                                                 : __ushort_as_half((unsigned short)0);
            }
        p0 = ab[L2BASE * 32 + l]; p1 = ab[(L2BASE + 1) * 32 + l];
        __syncthreads();

        // ---- layer 2 ----
#pragma unroll
        for (int nt = 0; nt < 4; nt++)
#pragma unroll
            for (int d = 0; d < 4; d++) acc[nt][d] = 0.f;
        gemm256(sS1, ab, L2BASE, acc, l, p0, p1);
#pragma unroll
        for (int nt = 0; nt < 4; nt++)
#pragma unroll
            for (int d = 0; d < 4; d++) {
                int rh = d >> 1, c = d & 1;
                float cur = acc[nt][d] + bias2[rh];
                float mo = m2[nt][d];
                float mn = BETA * mo + cur - ((mo > THRESH) ? THRESH : 0.0f);
                m2[nt][d] = mn;
                int j = jw + (l >> 2) + rh * 8;
                int b = nt * 8 + (l & 3) * 2 + c;
                sS2[b * SKS + j] = (mn > THRESH) ? __ushort_as_half((unsigned short)0x3C00)
                                                 : __ushort_as_half((unsigned short)0);
            }
        p0 = ab[L3BASE * 32 + l]; p1 = ab[(L3BASE + 1) * 32 + l];
        __syncthreads();

        // ---- layer 3 (membrane in SMEM) ----
#pragma unroll
        for (int nt = 0; nt < 4; nt++)
#pragma unroll
            for (int d = 0; d < 4; d++) acc[nt][d] = 0.f;
        gemm256(sS2, ab, L3BASE, acc, l, p0, p1);
#pragma unroll
        for (int nt = 0; nt < 4; nt++)
#pragma unroll
            for (int d = 0; d < 4; d++) {
                int rh = d >> 1, c = d & 1;
                float cur = acc[nt][d] + bias3[rh];
                int j = jw + (l >> 2) + rh * 8;
                int b = nt * 8 + (l & 3) * 2 + c;
                float mo = m3f[j * 33 + b];
                float mn = BETA * mo + cur - ((mo > THRESH) ? THRESH : 0.0f);
                m3f[j * 33 + b] = mn;
                s3f[j * 33 + b] = (mn > THRESH) ? 1.0f : 0.0f;
            }
        p0 = ab[0 * 32 + l]; p1 = ab[1 * 32 + l];   // prefetch L1 of t+1
        __syncthreads();

        // ---- layer 4: all 512 threads, 8 per output, shfl-tree reduce ----
        {
            float a = 0.f;
#pragma unroll 8
            for (int k = 0; k < 32; k++) {
                int i = part + 8 * k;
                a = fmaf(s3f[i * 33 + bb4], w4s[cc4 * NH + i], a);
            }
            a += __shfl_down_sync(0xffffffffu, a, 4, 8);
            a += __shfl_down_sync(0xffffffffu, a, 2, 8);
            a += __shfl_down_sync(0xffffffffu, a, 1, 8);
            if (part == 0) {
                float cur = a + b4v;
                float mo = m4v;
                float mn = BETA * mo + cur - ((mo > THRESH) ? THRESH : 0.0f);
                m4v = mn;
                out[(size_t)t * (BATCH * NC) + b0 * NC + o4] = (mn > THRESH) ? 1.0f : 0.0f;
            }
        }

        // stage x for t+1 (all threads)
        if (t + 1 < T) {
            for (int k = tid; k < NI * NB; k += NTHR) {
                int i = k >> 5, b = k & 31;
                float v = x[((size_t)(b0 + b) * NI + i) * T + t + 1];
                __half hh = __float2half_rn(v);
                __half hl = __float2half_rn(v - __half2float(hh));
                sXhi[b * SKX + i] = hh;
                sXlo[b * SKX + i] = hl;
            }
        }
        __syncthreads();
    }
}

extern "C" void kernel_launch(void* const* d_in, const int* in_sizes, int n_in,
                              void* d_out, int out_size) {
    const float* x  = (const float*)d_in[0];
    const float* W1 = (const float*)d_in[1];
    const float* b1 = (const float*)d_in[2];
    const float* W2 = (const float*)d_in[3];
    const float* b2 = (const float*)d_in[4];
    const float* W3 = (const float*)d_in[5];
    const float* b3 = (const float*)d_in[6];
    const float* W4 = (const float*)d_in[7];
    const float* b4 = (const float*)d_in[8];
    float* out = (float*)d_out;

    prep<<<(16 * FPW * 256 + 255) / 256, 256>>>(W1, W2, W3);

    const int smem_bytes = (2 * 32 * SKX + 2 * 32 * SKS) * 2
                         + (2 * 256 * 33 + NC * NH) * 4;
    cudaFuncSetAttribute(snn_kernel,
                         cudaFuncAttributeMaxDynamicSharedMemorySize, smem_bytes);
    snn_kernel<<<NBLK, NTHR, smem_bytes>>>(x, b1, b2, b3, W4, b4, out);
}

// round 10
// speedup vs baseline: 1.0676x; 1.0676x over previous
#include <cuda_runtime.h>
#include <cuda_fp16.h>
#include <cstdint>

#define BETA   0.95f
#define THRESH 1.0f

constexpr int NI = 80, NH = 256, NC = 2, T = 200, BATCH = 4096;
constexpr int NB = 32, NBLK = BATCH / NB, NTHR = 512;   // 16 warps, j-tile 16

// Per-warp A-frag stream (dedup'd): L1: 10 (kc0..4 x {hi,lo}), L2: 32, L3: 32
constexpr int FPW = 74, L2BASE = 10, L3BASE = 42;
__device__ __align__(16) __half g_wfrag[16 * FPW * 256];   // 606 KB, L2-resident

// Conflict-free strides (LDS.32 pattern: word%32 = r*4+q, bijective)
constexpr int SKX = 88;    // x tiles [32 b][80 i] halfs
constexpr int SKS = 264;   // spike tiles [32 b][256 i] halfs

// ---- prep: pack split weights into m16n8k16 A-frag lane order ----
__global__ void prep(const float* __restrict__ W1, const float* __restrict__ W2,
                     const float* __restrict__ W3) {
    int idx = blockIdx.x * 256 + threadIdx.x;      // 16*74*256
    if (idx >= 16 * FPW * 256) return;
    int h = idx & 7;
    int l = (idx >> 3) & 31;
    int f = (idx >> 8) % FPW;
    int w = (idx >> 8) / FPW;
    const float* W; int K, kc, split;
    if (f < L2BASE)      { kc = f >> 1; split = f & 1; W = W1; K = NI; }
    else if (f < L3BASE) { int g = f - L2BASE; kc = g >> 1; split = g & 1; W = W2; K = NH; }
    else                 { int g = f - L3BASE; kc = g >> 1; split = g & 1; W = W3; K = NH; }
    int r = (l >> 2) + ((h >> 1) & 1) * 8;
    int k = (l & 3) * 2 + (h & 1) + ((h >> 2) & 1) * 8;
    int j = w * 16 + r;
    int i = kc * 16 + k;
    float v = W[j * K + i];
    __half hv = __float2half_rn(v);
    if (split) hv = __float2half_rn(v - __half2float(hv));
    g_wfrag[idx] = hv;
}

__device__ __forceinline__ void mma16816(float* d, uint4 a, uint32_t b0, uint32_t b1) {
    asm volatile(
        "mma.sync.aligned.m16n8k16.row.col.f32.f16.f16.f32 "
        "{%0,%1,%2,%3}, {%4,%5,%6,%7}, {%8,%9}, {%0,%1,%2,%3};"
        : "+f"(d[0]), "+f"(d[1]), "+f"(d[2]), "+f"(d[3])
        : "r"(a.x), "r"(a.y), "r"(a.z), "r"(a.w), "r"(b0), "r"(b1));
}

// Register-free L1 prefetch (no dest reg -> no pressure at the 128-reg cap)
__device__ __forceinline__ void pfL1(const void* p) {
    asm volatile("prefetch.global.L1 [%0];" :: "l"(p));
}

// L2/L3: D[16j x 32b] += Wsplit * spikes. Depth-1 register prefetch (round 8)
// + depth-3 L1 prefetch (register-free).
__device__ __forceinline__ void gemm256(const __half* __restrict__ sB,
                                        const uint4* __restrict__ ab, int base,
                                        float acc[4][4], int l, uint4 a0, uint4 a1) {
    const int q2 = (l & 3) * 2, rw = (l >> 2);
    pfL1(&ab[(base + 4) * 32 + l]);    // kc2 lines
    pfL1(&ab[(base + 5) * 32 + l]);
#pragma unroll
    for (int kc = 0; kc < 16; kc++) {
        uint4 n0, n1;
        if (kc < 15) {
            n0 = ab[(base + 2 * kc + 2) * 32 + l];
            n1 = ab[(base + 2 * kc + 3) * 32 + l];
        }
        if (kc < 13) {                 // warm kc+3 lines
            pfL1(&ab[(base + 2 * kc + 6) * 32 + l]);
            pfL1(&ab[(base + 2 * kc + 7) * 32 + l]);
        }
        uint32_t bf[4][2];
#pragma unroll
        for (int nt = 0; nt < 4; nt++) {
            const uint32_t* p = (const uint32_t*)(sB + (nt * 8 + rw) * SKS + kc * 16 + q2);
            bf[nt][0] = p[0];
            bf[nt][1] = p[4];          // k+8
        }
#pragma unroll
        for (int nt = 0; nt < 4; nt++) mma16816(acc[nt], a0, bf[nt][0], bf[nt][1]);
#pragma unroll
        for (int nt = 0; nt < 4; nt++) mma16816(acc[nt], a1, bf[nt][0], bf[nt][1]);
        a0 = n0; a1 = n1;
    }
}

// L1: products hiW*hiX, hiW*loX, loW*hiX over K=80 (hi frag reused in-register)
__device__ __forceinline__ void gemm80(const __half* __restrict__ sXhi,
                                       const __half* __restrict__ sXlo,
                                       const uint4* __restrict__ ab,
                                       float acc[4][4], int l, uint4 ah, uint4 al) {
    const int q2 = (l & 3) * 2, rw = (l >> 2);
    pfL1(&ab[4 * 32 + l]);             // kc2 lines
    pfL1(&ab[5 * 32 + l]);
#pragma unroll
    for (int kc = 0; kc < 5; kc++) {
        uint4 nh, nl;
        if (kc < 4) {
            nh = ab[(2 * kc + 2) * 32 + l];
            nl = ab[(2 * kc + 3) * 32 + l];
        }
        if (kc < 2) {                  // warm kc+3 lines
            pfL1(&ab[(2 * kc + 6) * 32 + l]);
            pfL1(&ab[(2 * kc + 7) * 32 + l]);
        }
        uint32_t bh[4][2], bl[4][2];
#pragma unroll
        for (int nt = 0; nt < 4; nt++) {
            int off = (nt * 8 + rw) * SKX + kc * 16 + q2;
            const uint32_t* ph = (const uint32_t*)(sXhi + off);
            const uint32_t* pl = (const uint32_t*)(sXlo + off);
            bh[nt][0] = ph[0]; bh[nt][1] = ph[4];
            bl[nt][0] = pl[0]; bl[nt][1] = pl[4];
        }
#pragma unroll
        for (int nt = 0; nt < 4; nt++) mma16816(acc[nt], ah, bh[nt][0], bh[nt][1]);
#pragma unroll
        for (int nt = 0; nt < 4; nt++) mma16816(acc[nt], ah, bl[nt][0], bl[nt][1]);
#pragma unroll
        for (int nt = 0; nt < 4; nt++) mma16816(acc[nt], al, bh[nt][0], bh[nt][1]);
        ah = nh; al = nl;
    }
}

__global__ void __launch_bounds__(NTHR) snn_kernel(
    const float* __restrict__ x,
    const float* __restrict__ B1, const float* __restrict__ B2,
    const float* __restrict__ B3, const float* __restrict__ W4,
    const float* __restrict__ b4, float* __restrict__ out)
{
    extern __shared__ __align__(16) char smem[];
    __half* sXhi = (__half*)smem;                  // 32*88
    __half* sXlo = sXhi + 32 * SKX;
    __half* sS1  = sXlo + 32 * SKX;                // 32*264
    __half* sS2  = sS1 + 32 * SKS;
    float*  s3f  = (float*)(sS2 + 32 * SKS);       // [256 j][33]
    float*  w4s  = s3f + 256 * 33;                 // 512

    const int tid = threadIdx.x, l = tid & 31, w = tid >> 5;
    const int b0 = blockIdx.x * NB;
    const int jw = w * 16;
    const uint4* ab = ((const uint4*)g_wfrag) + (size_t)w * FPW * 32;

    float bias1[2], bias2[2], bias3[2];
#pragma unroll
    for (int rh = 0; rh < 2; rh++) {
        int j = jw + (l >> 2) + rh * 8;
        bias1[rh] = B1[j]; bias2[rh] = B2[j]; bias3[rh] = B3[j];
    }

    float m1[4][4], m2[4][4], m3[4][4];
#pragma unroll
    for (int nt = 0; nt < 4; nt++)
#pragma unroll
        for (int d = 0; d < 4; d++) { m1[nt][d] = 0.f; m2[nt][d] = 0.f; m3[nt][d] = 0.f; }

    float m4v = 0.f, b4v = 0.f;
    if (tid < NB * NC) b4v = b4[tid & 1];
    for (int k = tid; k < NC * NH; k += NTHR) w4s[k] = W4[k];

    // stage x for t=0
    for (int k = tid; k < NI * NB; k += NTHR) {
        int i = k >> 5, b = k & 31;
        float v = x[((size_t)(b0 + b) * NI + i) * T];
        __half hh = __float2half_rn(v);
        __half hl = __float2half_rn(v - __half2float(hh));
        sXhi[b * SKX + i] = hh;
        sXlo[b * SKX + i] = hl;
    }
    uint4 p0 = ab[0 * 32 + l], p1 = ab[1 * 32 + l];   // L1 kc=0 prefetch
    __syncthreads();

    for (int t = 0; t < T; t++) {
        float acc[4][4];

        // ---- layer 1 ----
#pragma unroll
        for (int nt = 0; nt < 4; nt++)
#pragma unroll
            for (int d = 0; d < 4; d++) acc[nt][d] = 0.f;
        gemm80(sXhi, sXlo, ab, acc, l, p0, p1);
#pragma unroll
        for (int nt = 0; nt < 4; nt++)
#pragma unroll
            for (int d = 0; d < 4; d++) {
                int rh = d >> 1, c = d & 1;
                float cur = acc[nt][d] + bias1[rh];
                float mo = m1[nt][d];
                float mn = BETA * mo + cur - ((mo > THRESH) ? THRESH : 0.0f);
                m1[nt][d] = mn;
                int j = jw + (l >> 2) + rh * 8;
                int b = nt * 8 + (l & 3) * 2 + c;
                sS1[b * SKS + j] = (mn > THRESH) ? __ushort_as_half((unsigned short)0x3C00)
                                                 : __ushort_as_half((unsigned short)0);
            }
        p0 = ab[L2BASE * 32 + l]; p1 = ab[(L2BASE + 1) * 32 + l];
        pfL1(&ab[(L2BASE + 2) * 32 + l]); pfL1(&ab[(L2BASE + 3) * 32 + l]);
        __syncthreads();

        // ---- layer 2 ----
#pragma unroll
        for (int nt = 0; nt < 4; nt++)
#pragma unroll
            for (int d = 0; d < 4; d++) acc[nt][d] = 0.f;
        gemm256(sS1, ab, L2BASE, acc, l, p0, p1);
#pragma unroll
        for (int nt = 0; nt < 4; nt++)
#pragma unroll
            for (int d = 0; d < 4; d++) {
                int rh = d >> 1, c = d & 1;
                float cur = acc[nt][d] + bias2[rh];
                float mo = m2[nt][d];
                float mn = BETA * mo + cur - ((mo > THRESH) ? THRESH : 0.0f);
                m2[nt][d] = mn;
                int j = jw + (l >> 2) + rh * 8;
                int b = nt * 8 + (l & 3) * 2 + c;
                sS2[b * SKS + j] = (mn > THRESH) ? __ushort_as_half((unsigned short)0x3C00)
                                                 : __ushort_as_half((unsigned short)0);
            }
        p0 = ab[L3BASE * 32 + l]; p1 = ab[(L3BASE + 1) * 32 + l];
        pfL1(&ab[(L3BASE + 2) * 32 + l]); pfL1(&ab[(L3BASE + 3) * 32 + l]);
        __syncthreads();

        // ---- layer 3 ----
#pragma unroll
        for (int nt = 0; nt < 4; nt++)
#pragma unroll
            for (int d = 0; d < 4; d++) acc[nt][d] = 0.f;
        gemm256(sS2, ab, L3BASE, acc, l, p0, p1);
#pragma unroll
        for (int nt = 0; nt < 4; nt++)
#pragma unroll
            for (int d = 0; d < 4; d++) {
                int rh = d >> 1, c = d & 1;
                float cur = acc[nt][d] + bias3[rh];
                float mo = m3[nt][d];
                float mn = BETA * mo + cur - ((mo > THRESH) ? THRESH : 0.0f);
                m3[nt][d] = mn;
                int j = jw + (l >> 2) + rh * 8;
                int b = nt * 8 + (l & 3) * 2 + c;
                s3f[j * 33 + b] = (mn > THRESH) ? 1.0f : 0.0f;
            }
        p0 = ab[0 * 32 + l]; p1 = ab[1 * 32 + l];   // prefetch L1 of t+1
        pfL1(&ab[2 * 32 + l]); pfL1(&ab[3 * 32 + l]);
        __syncthreads();

        // ---- layer 4 (tid<64) overlapped with x-staging of t+1 (tid>=64) ----
        if (tid < NB * NC) {
            int b = tid >> 1, c = tid & 1;
            const float* sr = s3f + b;
            const float* wr = w4s + c * NH;
            float a0 = b4v, a1 = 0.f, a2 = 0.f, a3 = 0.f;
#pragma unroll 8
            for (int i = 0; i < NH; i += 4) {
                a0 = fmaf(sr[(i + 0) * 33], wr[i + 0], a0);
                a1 = fmaf(sr[(i + 1) * 33], wr[i + 1], a1);
                a2 = fmaf(sr[(i + 2) * 33], wr[i + 2], a2);
                a3 = fmaf(sr[(i + 3) * 33], wr[i + 3], a3);
            }
            float cur = (a0 + a1) + (a2 + a3);
            float mo = m4v;
            float mn = BETA * mo + cur - ((mo > THRESH) ? THRESH : 0.0f);
            m4v = mn;
            out[(size_t)t * (BATCH * NC) + b0 * NC + tid] = (mn > THRESH) ? 1.0f : 0.0f;
        } else if (t + 1 < T) {
            for (int k = tid - 64; k < NI * NB; k += NTHR - 64) {
                int i = k >> 5, b = k & 31;
                float v = x[((size_t)(b0 + b) * NI + i) * T + t + 1];
                __half hh = __float2half_rn(v);
                __half hl = __float2half_rn(v - __half2float(hh));
                sXhi[b * SKX + i] = hh;
                sXlo[b * SKX + i] = hl;
            }
        }
        __syncthreads();
    }
}

extern "C" void kernel_launch(void* const* d_in, const int* in_sizes, int n_in,
                              void* d_out, int out_size) {
    const float* x  = (const float*)d_in[0];
    const float* W1 = (const float*)d_in[1];
    const float* b1 = (const float*)d_in[2];
    const float* W2 = (const float*)d_in[3];
    const float* b2 = (const float*)d_in[4];
    const float* W3 = (const float*)d_in[5];
    const float* b3 = (const float*)d_in[6];
    const float* W4 = (const float*)d_in[7];
    const float* b4 = (const float*)d_in[8];
    float* out = (float*)d_out;

    prep<<<(16 * FPW * 256 + 255) / 256, 256>>>(W1, W2, W3);

    const int smem_bytes = (2 * 32 * SKX + 2 * 32 * SKS) * 2
                         + (256 * 33 + NC * NH) * 4;
    cudaFuncSetAttribute(snn_kernel,
                         cudaFuncAttributeMaxDynamicSharedMemorySize, smem_bytes);
    snn_kernel<<<NBLK, NTHR, smem_bytes>>>(x, b1, b2, b3, W4, b4, out);
}

// round 11
// speedup vs baseline: 1.2745x; 1.1938x over previous
#include <cuda_runtime.h>
#include <cuda_fp16.h>
#include <cstdint>

#define BETA   0.95f
#define THRESH 1.0f

constexpr int NI = 80, NH = 256, NC = 2, T = 200, BATCH = 4096;
constexpr int NB = 32, NBLK = BATCH / NB, NTHR = 512;   // 16 warps, j-tile 16

// Per-warp A-frag stream (dedup'd): L1: 10 (kc0..4 x {hi,lo}), L2: 32, L3: 32
constexpr int FPW = 74, L2BASE = 10, L3BASE = 42;
__device__ __align__(16) __half g_wfrag[16 * FPW * 256];   // 606 KB, L2-resident

// Conflict-free strides (LDS.32 pattern: word%32 = r*4+q, bijective)
constexpr int SKX = 88;    // x tiles [32 b][80 i] halfs
constexpr int SKS = 264;   // spike tiles [32 b][256 i] halfs
constexpr int SXSZ = 32 * SKX;   // one x buffer (halfs)

// ---- prep: pack split weights into m16n8k16 A-frag lane order ----
__global__ void prep(const float* __restrict__ W1, const float* __restrict__ W2,
                     const float* __restrict__ W3) {
    int idx = blockIdx.x * 256 + threadIdx.x;      // 16*74*256
    if (idx >= 16 * FPW * 256) return;
    int h = idx & 7;
    int l = (idx >> 3) & 31;
    int f = (idx >> 8) % FPW;
    int w = (idx >> 8) / FPW;
    const float* W; int K, kc, split;
    if (f < L2BASE)      { kc = f >> 1; split = f & 1; W = W1; K = NI; }
    else if (f < L3BASE) { int g = f - L2BASE; kc = g >> 1; split = g & 1; W = W2; K = NH; }
    else                 { int g = f - L3BASE; kc = g >> 1; split = g & 1; W = W3; K = NH; }
    int r = (l >> 2) + ((h >> 1) & 1) * 8;
    int k = (l & 3) * 2 + (h & 1) + ((h >> 2) & 1) * 8;
    int j = w * 16 + r;
    int i = kc * 16 + k;
    float v = W[j * K + i];
    __half hv = __float2half_rn(v);
    if (split) hv = __float2half_rn(v - __half2float(hv));
    g_wfrag[idx] = hv;
}

__device__ __forceinline__ void mma16816(float* d, uint4 a, uint32_t b0, uint32_t b1) {
    asm volatile(
        "mma.sync.aligned.m16n8k16.row.col.f32.f16.f16.f32 "
        "{%0,%1,%2,%3}, {%4,%5,%6,%7}, {%8,%9}, {%0,%1,%2,%3};"
        : "+f"(d[0]), "+f"(d[1]), "+f"(d[2]), "+f"(d[3])
        : "r"(a.x), "r"(a.y), "r"(a.z), "r"(a.w), "r"(b0), "r"(b1));
}

// L2/L3: D[16j x 32b] += Wsplit * spikes. Depth-1 register A-prefetch.
__device__ __forceinline__ void gemm256(const __half* __restrict__ sB,
                                        const uint4* __restrict__ ab, int base,
                                        float acc[4][4], int l, uint4 a0, uint4 a1) {
    const int q2 = (l & 3) * 2, rw = (l >> 2);
#pragma unroll
    for (int kc = 0; kc < 16; kc++) {
        uint4 n0, n1;
        if (kc < 15) {
            n0 = ab[(base + 2 * kc + 2) * 32 + l];
            n1 = ab[(base + 2 * kc + 3) * 32 + l];
        }
        uint32_t bf[4][2];
#pragma unroll
        for (int nt = 0; nt < 4; nt++) {
            const uint32_t* p = (const uint32_t*)(sB + (nt * 8 + rw) * SKS + kc * 16 + q2);
            bf[nt][0] = p[0];
            bf[nt][1] = p[4];          // k+8
        }
#pragma unroll
        for (int nt = 0; nt < 4; nt++) mma16816(acc[nt], a0, bf[nt][0], bf[nt][1]);
#pragma unroll
        for (int nt = 0; nt < 4; nt++) mma16816(acc[nt], a1, bf[nt][0], bf[nt][1]);
        a0 = n0; a1 = n1;
    }
}

// L1: products hiW*hiX, hiW*loX, loW*hiX over K=80 (hi frag reused in-register)
__device__ __forceinline__ void gemm80(const __half* __restrict__ sXhi,
                                       const __half* __restrict__ sXlo,
                                       const uint4* __restrict__ ab,
                                       float acc[4][4], int l, uint4 ah, uint4 al) {
    const int q2 = (l & 3) * 2, rw = (l >> 2);
#pragma unroll
    for (int kc = 0; kc < 5; kc++) {
        uint4 nh, nl;
        if (kc < 4) {
            nh = ab[(2 * kc + 2) * 32 + l];
            nl = ab[(2 * kc + 3) * 32 + l];
        }
        uint32_t bh[4][2], bl[4][2];
#pragma unroll
        for (int nt = 0; nt < 4; nt++) {
            int off = (nt * 8 + rw) * SKX + kc * 16 + q2;
            const uint32_t* ph = (const uint32_t*)(sXhi + off);
            const uint32_t* pl = (const uint32_t*)(sXlo + off);
            bh[nt][0] = ph[0]; bh[nt][1] = ph[4];
            bl[nt][0] = pl[0]; bl[nt][1] = pl[4];
        }
#pragma unroll
        for (int nt = 0; nt < 4; nt++) mma16816(acc[nt], ah, bh[nt][0], bh[nt][1]);
#pragma unroll
        for (int nt = 0; nt < 4; nt++) mma16816(acc[nt], ah, bl[nt][0], bl[nt][1]);
#pragma unroll
        for (int nt = 0; nt < 4; nt++) mma16816(acc[nt], al, bh[nt][0], bh[nt][1]);
        ah = nh; al = nl;
    }
}

// Stage 4 timesteps of x (t0..t0+3, t0%4==0) into the 4-deep SMEM ring.
// One float4 LDG per (b,i): t-contiguous -> 4 steps share the same 32 lines.
__device__ __forceinline__ void stage_x4(const float* __restrict__ x, __half* sX,
                                         int b0, int t0, int start, int stride) {
    for (int k = start; k < NI * NB; k += stride) {
        int b = k / NI, i = k - b * NI;
        float4 v = *(const float4*)(x + ((size_t)(b0 + b) * NI + i) * T + t0);
        float vv[4] = { v.x, v.y, v.z, v.w };
#pragma unroll
        for (int tt = 0; tt < 4; tt++) {
            __half hh = __float2half_rn(vv[tt]);
            __half hl = __float2half_rn(vv[tt] - __half2float(hh));
            sX[(tt * 2 + 0) * SXSZ + b * SKX + i] = hh;
            sX[(tt * 2 + 1) * SXSZ + b * SKX + i] = hl;
        }
    }
}

__global__ void __launch_bounds__(NTHR) snn_kernel(
    const float* __restrict__ x,
    const float* __restrict__ B1, const float* __restrict__ B2,
    const float* __restrict__ B3, const float* __restrict__ W4,
    const float* __restrict__ b4, float* __restrict__ out)
{
    extern __shared__ __align__(16) char smem[];
    __half* sX   = (__half*)smem;                  // [4 tt][2 hi/lo][32*88]
    __half* sS1  = sX + 8 * SXSZ;                  // 32*264
    __half* sS2  = sS1 + 32 * SKS;
    float*  s3f  = (float*)(sS2 + 32 * SKS);       // [256 j][33]
    float*  w4s  = s3f + 256 * 33;                 // 512

    const int tid = threadIdx.x, l = tid & 31, w = tid >> 5;
    const int b0 = blockIdx.x * NB;
    const int jw = w * 16;
    const uint4* ab = ((const uint4*)g_wfrag) + (size_t)w * FPW * 32;

    float bias1[2], bias2[2], bias3[2];
#pragma unroll
    for (int rh = 0; rh < 2; rh++) {
        int j = jw + (l >> 2) + rh * 8;
        bias1[rh] = B1[j]; bias2[rh] = B2[j]; bias3[rh] = B3[j];
    }

    float m1[4][4], m2[4][4], m3[4][4];
#pragma unroll
    for (int nt = 0; nt < 4; nt++)
#pragma unroll
        for (int d = 0; d < 4; d++) { m1[nt][d] = 0.f; m2[nt][d] = 0.f; m3[nt][d] = 0.f; }

    float m4v = 0.f, b4v = 0.f;
    if (tid < NB * NC) b4v = b4[tid & 1];
    for (int k = tid; k < NC * NH; k += NTHR) w4s[k] = W4[k];

    // stage x for steps 0..3 (all threads)
    stage_x4(x, sX, b0, 0, tid, NTHR);
    uint4 p0 = ab[0 * 32 + l], p1 = ab[1 * 32 + l];   // L1 kc=0 prefetch
    __syncthreads();

    for (int t = 0; t < T; t++) {
        const __half* sXhi = sX + ((t & 3) * 2) * SXSZ;
        const __half* sXlo = sXhi + SXSZ;
        float acc[4][4];

        // ---- layer 1 ----
#pragma unroll
        for (int nt = 0; nt < 4; nt++)
#pragma unroll
            for (int d = 0; d < 4; d++) acc[nt][d] = 0.f;
        gemm80(sXhi, sXlo, ab, acc, l, p0, p1);
#pragma unroll
        for (int nt = 0; nt < 4; nt++)
#pragma unroll
            for (int d = 0; d < 4; d++) {
                int rh = d >> 1, c = d & 1;
                float cur = acc[nt][d] + bias1[rh];
                float mo = m1[nt][d];
                float mn = BETA * mo + cur - ((mo > THRESH) ? THRESH : 0.0f);
                m1[nt][d] = mn;
                int j = jw + (l >> 2) + rh * 8;
                int b = nt * 8 + (l & 3) * 2 + c;
                sS1[b * SKS + j] = (mn > THRESH) ? __ushort_as_half((unsigned short)0x3C00)
                                                 : __ushort_as_half((unsigned short)0);
            }
        p0 = ab[L2BASE * 32 + l]; p1 = ab[(L2BASE + 1) * 32 + l];
        __syncthreads();

        // ---- layer 2 ----
#pragma unroll
        for (int nt = 0; nt < 4; nt++)
#pragma unroll
            for (int d = 0; d < 4; d++) acc[nt][d] = 0.f;
        gemm256(sS1, ab, L2BASE, acc, l, p0, p1);
#pragma unroll
        for (int nt = 0; nt < 4; nt++)
#pragma unroll
            for (int d = 0; d < 4; d++) {
                int rh = d >> 1, c = d & 1;
                float cur = acc[nt][d] + bias2[rh];
                float mo = m2[nt][d];
                float mn = BETA * mo + cur - ((mo > THRESH) ? THRESH : 0.0f);
                m2[nt][d] = mn;
                int j = jw + (l >> 2) + rh * 8;
                int b = nt * 8 + (l & 3) * 2 + c;
                sS2[b * SKS + j] = (mn > THRESH) ? __ushort_as_half((unsigned short)0x3C00)
                                                 : __ushort_as_half((unsigned short)0);
            }
        p0 = ab[L3BASE * 32 + l]; p1 = ab[(L3BASE + 1) * 32 + l];
        __syncthreads();

        // ---- layer 3 ----
#pragma unroll
        for (int nt = 0; nt < 4; nt++)
#pragma unroll
            for (int d = 0; d < 4; d++) acc[nt][d] = 0.f;
        gemm256(sS2, ab, L3BASE, acc, l, p0, p1);
#pragma unroll
        for (int nt = 0; nt < 4; nt++)
#pragma unroll
            for (int d = 0; d < 4; d++) {
                int rh = d >> 1, c = d & 1;
                float cur = acc[nt][d] + bias3[rh];
                float mo = m3[nt][d];
                float mn = BETA * mo + cur - ((mo > THRESH) ? THRESH : 0.0f);
                m3[nt][d] = mn;
                int j = jw + (l >> 2) + rh * 8;
                int b = nt * 8 + (l & 3) * 2 + c;
                s3f[j * 33 + b] = (mn > THRESH) ? 1.0f : 0.0f;
            }
        p0 = ab[0 * 32 + l]; p1 = ab[1 * 32 + l];   // prefetch L1 of t+1
        __syncthreads();

        // ---- layer 4 (tid<64) overlapped with x-staging every 4th step ----
        if (tid < NB * NC) {
            int b = tid >> 1, c = tid & 1;
            const float* sr = s3f + b;
            const float* wr = w4s + c * NH;
            float a0 = b4v, a1 = 0.f, a2 = 0.f, a3 = 0.f;
#pragma unroll 8
            for (int i = 0; i < NH; i += 4) {
                a0 = fmaf(sr[(i + 0) * 33], wr[i + 0], a0);
                a1 = fmaf(sr[(i + 1) * 33], wr[i + 1], a1);
                a2 = fmaf(sr[(i + 2) * 33], wr[i + 2], a2);
                a3 = fmaf(sr[(i + 3) * 33], wr[i + 3], a3);
            }
            float cur = (a0 + a1) + (a2 + a3);
            float mo = m4v;
            float mn = BETA * mo + cur - ((mo > THRESH) ? THRESH : 0.0f);
            m4v = mn;
            out[(size_t)t * (BATCH * NC) + b0 * NC + tid] = (mn > THRESH) ? 1.0f : 0.0f;
        } else if ((t & 3) == 3 && t + 1 < T) {
            // stage next 4 steps (t+1 .. t+4), threads 64..511
            stage_x4(x, sX, b0, t + 1, tid - 64, NTHR - 64);
        }
        __syncthreads();
    }
}

extern "C" void kernel_launch(void* const* d_in, const int* in_sizes, int n_in,
                              void* d_out, int out_size) {
    const float* x  = (const float*)d_in[0];
    const float* W1 = (const float*)d_in[1];
    const float* b1 = (const float*)d_in[2];
    const float* W2 = (const float*)d_in[3];
    const float* b2 = (const float*)d_in[4];
    const float* W3 = (const float*)d_in[5];
    const float* b3 = (const float*)d_in[6];
    const float* W4 = (const float*)d_in[7];
    const float* b4 = (const float*)d_in[8];
    float* out = (float*)d_out;

    prep<<<(16 * FPW * 256 + 255) / 256, 256>>>(W1, W2, W3);

    const int smem_bytes = (8 * SXSZ + 2 * 32 * SKS) * 2
                         + (256 * 33 + NC * NH) * 4;
    cudaFuncSetAttribute(snn_kernel,
                         cudaFuncAttributeMaxDynamicSharedMemorySize, smem_bytes);
    snn_kernel<<<NBLK, NTHR, smem_bytes>>>(x, b1, b2, b3, W4, b4, out);
}

// round 12
// speedup vs baseline: 1.3013x; 1.0210x over previous
#include <cuda_runtime.h>
#include <cuda_fp16.h>
#include <cstdint>

#define BETA   0.95f
#define THRESH 1.0f

constexpr int NI = 80, NH = 256, NC = 2, T = 200, BATCH = 4096;
constexpr int NB = 32, NBLK = BATCH / NB, NTHR = 512;   // 16 warps, j-tile 16

// Per-warp A-frag stream (dedup'd): L1: 10 (kc0..4 x {hi,lo}), L2: 32, L3: 32
constexpr int FPW = 74, L2BASE = 10, L3BASE = 42;
__device__ __align__(16) __half g_wfrag[16 * FPW * 256];   // 606 KB, L2-resident

// LDS.64-conflict-free strides: word-stride mod 32 == 8
// SKS = 272 halfs (136 words), SKX = 80 halfs (40 words, no padding).
constexpr int SKX = 80;
constexpr int SKS = 272;
constexpr int SXSZ = 32 * SKX;   // one x buffer (halfs)

// k-interleave within each 16-k block: pairs (k,k+8) adjacent so one LDS.64
// yields both mma B operands. pos(2q)=4q, pos(2q+1)=4q+1, pos(2q+8)=4q+2, ...
__host__ __device__ __forceinline__ int fintl(int kk) {
    return ((kk & 6) << 1) | (kk & 1) | ((kk & 8) >> 2);
}

// ---- prep: pack split weights into m16n8k16 A-frag lane order ----
__global__ void prep(const float* __restrict__ W1, const float* __restrict__ W2,
                     const float* __restrict__ W3) {
    int idx = blockIdx.x * 256 + threadIdx.x;      // 16*74*256
    if (idx >= 16 * FPW * 256) return;
    int h = idx & 7;
    int l = (idx >> 3) & 31;
    int f = (idx >> 8) % FPW;
    int w = (idx >> 8) / FPW;
    const float* W; int K, kc, split;
    if (f < L2BASE)      { kc = f >> 1; split = f & 1; W = W1; K = NI; }
    else if (f < L3BASE) { int g = f - L2BASE; kc = g >> 1; split = g & 1; W = W2; K = NH; }
    else                 { int g = f - L3BASE; kc = g >> 1; split = g & 1; W = W3; K = NH; }
    int r = (l >> 2) + ((h >> 1) & 1) * 8;
    int k = (l & 3) * 2 + (h & 1) + ((h >> 2) & 1) * 8;
    int j = w * 16 + r;
    int i = kc * 16 + k;
    float v = W[j * K + i];
    __half hv = __float2half_rn(v);
    if (split) hv = __float2half_rn(v - __half2float(hv));
    g_wfrag[idx] = hv;
}

__device__ __forceinline__ void mma16816(float* d, uint4 a, uint32_t b0, uint32_t b1) {
    asm volatile(
        "mma.sync.aligned.m16n8k16.row.col.f32.f16.f16.f32 "
        "{%0,%1,%2,%3}, {%4,%5,%6,%7}, {%8,%9}, {%0,%1,%2,%3};"
        : "+f"(d[0]), "+f"(d[1]), "+f"(d[2]), "+f"(d[3])
        : "r"(a.x), "r"(a.y), "r"(a.z), "r"(a.w), "r"(b0), "r"(b1));
}

// L2/L3: D[16j x 32b] += Wsplit * spikes. One LDS.64 per B fragment.
__device__ __forceinline__ void gemm256(const __half* __restrict__ sB,
                                        const uint4* __restrict__ ab, int base,
                                        float acc[4][4], int l, uint4 a0, uint4 a1) {
    const int q4 = (l & 3) * 4, rw = (l >> 2);
#pragma unroll
    for (int kc = 0; kc < 16; kc++) {
        uint4 n0, n1;
        if (kc < 15) {
            n0 = ab[(base + 2 * kc + 2) * 32 + l];
            n1 = ab[(base + 2 * kc + 3) * 32 + l];
        }
        uint2 bf[4];
#pragma unroll
        for (int nt = 0; nt < 4; nt++)
            bf[nt] = *(const uint2*)(sB + (nt * 8 + rw) * SKS + kc * 16 + q4);
#pragma unroll
        for (int nt = 0; nt < 4; nt++) mma16816(acc[nt], a0, bf[nt].x, bf[nt].y);
#pragma unroll
        for (int nt = 0; nt < 4; nt++) mma16816(acc[nt], a1, bf[nt].x, bf[nt].y);
        a0 = n0; a1 = n1;
    }
}

// L1: products hiW*hiX, hiW*loX, loW*hiX over K=80 (hi frag reused in-register)
__device__ __forceinline__ void gemm80(const __half* __restrict__ sXhi,
                                       const __half* __restrict__ sXlo,
                                       const uint4* __restrict__ ab,
                                       float acc[4][4], int l, uint4 ah, uint4 al) {
    const int q4 = (l & 3) * 4, rw = (l >> 2);
#pragma unroll
    for (int kc = 0; kc < 5; kc++) {
        uint4 nh, nl;
        if (kc < 4) {
            nh = ab[(2 * kc + 2) * 32 + l];
            nl = ab[(2 * kc + 3) * 32 + l];
        }
        uint2 bh[4], bl[4];
#pragma unroll
        for (int nt = 0; nt < 4; nt++) {
            int off = (nt * 8 + rw) * SKX + kc * 16 + q4;
            bh[nt] = *(const uint2*)(sXhi + off);
            bl[nt] = *(const uint2*)(sXlo + off);
        }
#pragma unroll
        for (int nt = 0; nt < 4; nt++) mma16816(acc[nt], ah, bh[nt].x, bh[nt].y);
#pragma unroll
        for (int nt = 0; nt < 4; nt++) mma16816(acc[nt], ah, bl[nt].x, bl[nt].y);
#pragma unroll
        for (int nt = 0; nt < 4; nt++) mma16816(acc[nt], al, bh[nt].x, bh[nt].y);
        ah = nh; al = nl;
    }
}

// Stage 4 timesteps of x (t0..t0+3) into the 4-deep SMEM ring (interleaved pos).
__device__ __forceinline__ void stage_x4(const float* __restrict__ x, __half* sX,
                                         int b0, int t0, int start, int stride) {
    for (int k = start; k < NI * NB; k += stride) {
        int b = k / NI, i = k - b * NI;
        float4 v = *(const float4*)(x + ((size_t)(b0 + b) * NI + i) * T + t0);
        float vv[4] = { v.x, v.y, v.z, v.w };
        int off = b * SKX + (i >> 4) * 16 + fintl(i & 15);
#pragma unroll
        for (int tt = 0; tt < 4; tt++) {
            __half hh = __float2half_rn(vv[tt]);
            __half hl = __float2half_rn(vv[tt] - __half2float(hh));
            sX[(tt * 2 + 0) * SXSZ + off] = hh;
            sX[(tt * 2 + 1) * SXSZ + off] = hl;
        }
    }
}

__global__ void __launch_bounds__(NTHR) snn_kernel(
    const float* __restrict__ x,
    const float* __restrict__ B1, const float* __restrict__ B2,
    const float* __restrict__ B3, const float* __restrict__ W4,
    const float* __restrict__ b4, float* __restrict__ out)
{
    extern __shared__ __align__(16) char smem[];
    __half* sX   = (__half*)smem;                  // [4 tt][2 hi/lo][32*80]
    __half* sS1  = sX + 8 * SXSZ;                  // 32*272
    __half* sS2  = sS1 + 32 * SKS;
    float*  s3f  = (float*)(sS2 + 32 * SKS);       // [256 j][33]
    float*  w4s  = s3f + 256 * 33;                 // 512

    const int tid = threadIdx.x, l = tid & 31, w = tid >> 5;
    const int b0 = blockIdx.x * NB;
    const int jw = w * 16;
    const uint4* ab = ((const uint4*)g_wfrag) + (size_t)w * FPW * 32;

    // interleaved j-position within the warp's 16-j block (j&15 = (l>>2)+8*rh)
    int fj[2];
    {
        int r = l >> 2;
        fj[0] = ((r & 6) << 1) | (r & 1);
        fj[1] = fj[0] + 2;
    }

    float bias1[2], bias2[2], bias3[2];
#pragma unroll
    for (int rh = 0; rh < 2; rh++) {
        int j = jw + (l >> 2) + rh * 8;
        bias1[rh] = B1[j]; bias2[rh] = B2[j]; bias3[rh] = B3[j];
    }

    float m1[4][4], m2[4][4], m3[4][4];
#pragma unroll
    for (int nt = 0; nt < 4; nt++)
#pragma unroll
        for (int d = 0; d < 4; d++) { m1[nt][d] = 0.f; m2[nt][d] = 0.f; m3[nt][d] = 0.f; }

    float m4v = 0.f, b4v = 0.f;
    if (tid < NB * NC) b4v = b4[tid & 1];
    for (int k = tid; k < NC * NH; k += NTHR) w4s[k] = W4[k];

    // stage x for steps 0..3 (all threads)
    stage_x4(x, sX, b0, 0, tid, NTHR);
    uint4 p0 = ab[0 * 32 + l], p1 = ab[1 * 32 + l];   // L1 kc=0 prefetch
    __syncthreads();

    for (int t = 0; t < T; t++) {
        const __half* sXhi = sX + ((t & 3) * 2) * SXSZ;
        const __half* sXlo = sXhi + SXSZ;
        float acc[4][4];

        // ---- layer 1 ----
#pragma unroll
        for (int nt = 0; nt < 4; nt++)
#pragma unroll
            for (int d = 0; d < 4; d++) acc[nt][d] = 0.f;
        gemm80(sXhi, sXlo, ab, acc, l, p0, p1);
#pragma unroll
        for (int nt = 0; nt < 4; nt++)
#pragma unroll
            for (int d = 0; d < 4; d++) {
                int rh = d >> 1, c = d & 1;
                float cur = acc[nt][d] + bias1[rh];
                float mo = m1[nt][d];
                float mn = BETA * mo + cur - ((mo > THRESH) ? THRESH : 0.0f);
                m1[nt][d] = mn;
                int b = nt * 8 + (l & 3) * 2 + c;
                sS1[b * SKS + jw + fj[rh]] =
                    (mn > THRESH) ? __ushort_as_half((unsigned short)0x3C00)
                                  : __ushort_as_half((unsigned short)0);
            }
        p0 = ab[L2BASE * 32 + l]; p1 = ab[(L2BASE + 1) * 32 + l];
        __syncthreads();

        // ---- layer 2 ----
#pragma unroll
        for (int nt = 0; nt < 4; nt++)
#pragma unroll
            for (int d = 0; d < 4; d++) acc[nt][d] = 0.f;
        gemm256(sS1, ab, L2BASE, acc, l, p0, p1);
#pragma unroll
        for (int nt = 0; nt < 4; nt++)
#pragma unroll
            for (int d = 0; d < 4; d++) {
                int rh = d >> 1, c = d & 1;
                float cur = acc[nt][d] + bias2[rh];
                float mo = m2[nt][d];
                float mn = BETA * mo + cur - ((mo > THRESH) ? THRESH : 0.0f);
                m2[nt][d] = mn;
                int b = nt * 8 + (l & 3) * 2 + c;
                sS2[b * SKS + jw + fj[rh]] =
                    (mn > THRESH) ? __ushort_as_half((unsigned short)0x3C00)
                                  : __ushort_as_half((unsigned short)0);
            }
        p0 = ab[L3BASE * 32 + l]; p1 = ab[(L3BASE + 1) * 32 + l];
        __syncthreads();

        // ---- layer 3 ----
#pragma unroll
        for (int nt = 0; nt < 4; nt++)
#pragma unroll
            for (int d = 0; d < 4; d++) acc[nt][d] = 0.f;
        gemm256(sS2, ab, L3BASE, acc, l, p0, p1);
#pragma unroll
        for (int nt = 0; nt < 4; nt++)
#pragma unroll
            for (int d = 0; d < 4; d++) {
                int rh = d >> 1, c = d & 1;
                float cur = acc[nt][d] + bias3[rh];
                float mo = m3[nt][d];
                float mn = BETA * mo + cur - ((mo > THRESH) ? THRESH : 0.0f);
                m3[nt][d] = mn;
                int j = jw + (l >> 2) + rh * 8;
                int b = nt * 8 + (l & 3) * 2 + c;
                s3f[j * 33 + b] = (mn > THRESH) ? 1.0f : 0.0f;
            }
        p0 = ab[0 * 32 + l]; p1 = ab[1 * 32 + l];   // prefetch L1 of t+1
        __syncthreads();

        // ---- layer 4 (tid<64), x-staging every 4th step (tid>=64) ----
        if (tid < NB * NC) {
            int b = tid >> 1, c = tid & 1;
            const float* sr = s3f + b;
            const float* wr = w4s + c * NH;
            float a0 = b4v, a1 = 0.f, a2 = 0.f, a3 = 0.f;
#pragma unroll 8
            for (int i = 0; i < NH; i += 4) {
                a0 = fmaf(sr[(i + 0) * 33], wr[i + 0], a0);
                a1 = fmaf(sr[(i + 1) * 33], wr[i + 1], a1);
                a2 = fmaf(sr[(i + 2) * 33], wr[i + 2], a2);
                a3 = fmaf(sr[(i + 3) * 33], wr[i + 3], a3);
            }
            float cur = (a0 + a1) + (a2 + a3);
            float mo = m4v;
            float mn = BETA * mo + cur - ((mo > THRESH) ? THRESH : 0.0f);
            m4v = mn;
            out[(size_t)t * (BATCH * NC) + b0 * NC + tid] = (mn > THRESH) ? 1.0f : 0.0f;
        } else if ((t & 3) == 3 && t + 1 < T) {
            stage_x4(x, sX, b0, t + 1, tid - 64, NTHR - 64);
        }
        // Barrier needed only when x was staged: L4's s3f reads are ordered by
        // the reader threads' own barriers 1-2 of t+1 before s3f is rewritten.
        if ((t & 3) == 3) __syncthreads();
    }
}

extern "C" void kernel_launch(void* const* d_in, const int* in_sizes, int n_in,
                              void* d_out, int out_size) {
    const float* x  = (const float*)d_in[0];
    const float* W1 = (const float*)d_in[1];
    const float* b1 = (const float*)d_in[2];
    const float* W2 = (const float*)d_in[3];
    const float* b2 = (const float*)d_in[4];
    const float* W3 = (const float*)d_in[5];
    const float* b3 = (const float*)d_in[6];
    const float* W4 = (const float*)d_in[7];
    const float* b4 = (const float*)d_in[8];
    float* out = (float*)d_out;

    prep<<<(16 * FPW * 256 + 255) / 256, 256>>>(W1, W2, W3);

    const int smem_bytes = (8 * SXSZ + 2 * 32 * SKS) * 2
                         + (256 * 33 + NC * NH) * 4;
    cudaFuncSetAttribute(snn_kernel,
                         cudaFuncAttributeMaxDynamicSharedMemorySize, smem_bytes);
    snn_kernel<<<NBLK, NTHR, smem_bytes>>>(x, b1, b2, b3, W4, b4, out);
}